// round 14
// baseline (speedup 1.0000x reference)
#include <cuda_runtime.h>
#include <cuda_fp16.h>
#include <math.h>

// Problem constants (fixed shapes per reference)
#define V  4
#define T  4
#define NS 100000
#define NH 12288
#define E  100000
#define H  64
#define C  (V*T)          // 16 (v, t') edge-type combos
#define NEG 0.01f

#define QPC     (E/4)     // 25000 int4-quads per combo
#define HQUADS  (C*E/8)   // 200000 quads per half (8 combos)
#define HNODES  (2*NS)    // 200000 (v,s) nodes per half (2 vars)
#define HB      782       // blocks covering 200000 items at 256 threads
#define EPIHB   (192*8)   // 1536 epilogue blocks per half (192 strips x 8 vt)

// ---------------- scratch (__device__ globals; no allocation allowed) ----------------
__device__ unsigned g_deg_out_p[C*NS/4];  // packed u8 out-degree (4 nodes / word)  1.6 MB
__device__ int      g_deg_in  [C*NH];     // in-degree per (combo, dst-node)        0.8 MB
__device__ uint2    g_xnh     [C*NS];     // half4 normalized feats per combo      12.8 MB
__device__ float4   g_s4      [C*NH];     // s accumulators, t in components        3.0 MB

__device__ __forceinline__ float fixnum(float a) {
    if (isnan(a)) return 0.0f;
    if (isinf(a)) return a > 0.0f ? 3.4028234663852886e38f : -3.4028234663852886e38f;
    return a;
}

__device__ __forceinline__ void red_add_v4(float4* addr, float a, float b, float c, float d) {
    asm volatile("red.global.add.v4.f32 [%0], {%1, %2, %3, %4};"
                 :: "l"(addr), "f"(a), "f"(b), "f"(c), "f"(d) : "memory");
}

// ---- packed f32x2 helpers (Blackwell FFMA2) ----
__device__ __forceinline__ unsigned long long pk2(float a, float b) {
    unsigned long long r;
    asm("mov.b64 %0, {%1, %2};" : "=l"(r) : "f"(a), "f"(b));
    return r;
}
__device__ __forceinline__ void upk2(unsigned long long v, float& a, float& b) {
    asm("mov.b64 {%0, %1}, %2;" : "=f"(a), "=f"(b) : "l"(v));
}
__device__ __forceinline__ unsigned long long fma2(unsigned long long a,
                                                   unsigned long long b,
                                                   unsigned long long c) {
    unsigned long long r;
    asm("fma.rn.f32x2 %0, %1, %2, %3;" : "=l"(r) : "l"(a), "l"(b), "l"(c));
    return r;
}

// ================= task bodies =================

// degree counting for one edge quad (global quad index qi)
__device__ __forceinline__ void deg_body(int qi, int4 s, int4 d) {
    int c = qi / QPC;
    unsigned* dout = g_deg_out_p + c*(NS/4);
    int*      din  = g_deg_in    + c*NH;
    atomicAdd(&dout[s.x >> 2], 1u << ((s.x & 3) << 3));
    atomicAdd(&dout[s.y >> 2], 1u << ((s.y & 3) << 3));
    atomicAdd(&dout[s.z >> 2], 1u << ((s.z & 3) << 3));
    atomicAdd(&dout[s.w >> 2], 1u << ((s.w & 3) << 3));
    atomicAdd(&din[d.x], 1); atomicAdd(&din[d.y], 1);
    atomicAdd(&din[d.z], 1); atomicAdd(&din[d.w], 1);
}

// normalized-feature build for node j of a 2-var half (vbase in {0,2})
__device__ __forceinline__ void xn_body(int j, int vbase, float4 xv) {
    int v = vbase + j / NS;
    int s = j % NS;
#pragma unroll
    for (int tp = 0; tp < 4; tp++) {
        int c = v*4 + tp;
        unsigned w = g_deg_out_p[c*(NS/4) + (s >> 2)];
        int deg = (w >> ((s & 3) << 3)) & 255;
        float nrm = rsqrtf(fmaxf((float)deg, 1.0f));
        __half2 h0 = __floats2half2_rn(xv.x * nrm, xv.y * nrm);
        __half2 h1 = __floats2half2_rn(xv.z * nrm, xv.w * nrm);
        uint2 e;
        e.x = *reinterpret_cast<unsigned*>(&h0);
        e.y = *reinterpret_cast<unsigned*>(&h1);
        g_xnh[c*NS + s] = e;
    }
}

// scatter for one edge quad (global quad index qi)
__device__ __forceinline__ void scatter_body(int qi, int4 sq, int4 dq) {
    int c = qi / QPC;
    const uint2* __restrict__ xn = g_xnh + c*NS;
    float4*                   sc = g_s4  + c*NH;
    uint2 q0 = xn[sq.x];
    uint2 q1 = xn[sq.y];
    uint2 q2 = xn[sq.z];
    uint2 q3 = xn[sq.w];
#pragma unroll
    for (int k = 0; k < 4; k++) {
        uint2 q = (k == 0) ? q0 : (k == 1) ? q1 : (k == 2) ? q2 : q3;
        int   d = (k == 0) ? dq.x : (k == 1) ? dq.y : (k == 2) ? dq.z : dq.w;
        float2 f0 = __half22float2(*reinterpret_cast<__half2*>(&q.x));
        float2 f1 = __half22float2(*reinterpret_cast<__half2*>(&q.y));
        red_add_v4(&sc[d], f0.x, f0.y, f1.x, f1.y);
    }
}

// epilogue for one (vt, strip) tile; whole block takes this path (syncthreads-safe)
__device__ __forceinline__ void epi_body(int vt, int strip, int tid,
                                         float wv, float bv,   // preloaded Wp/Bp element
                                         float* __restrict__ out) {
    int v = vt >> 2;
    int t = vt & 3;
    (void)v;

    __shared__ float sW[T*H];
    __shared__ float sB[T*H];
    __shared__ float ss[T*64];
    sW[tid] = wv;
    sB[tid] = bv;
    {
        int tp = tid >> 6;
        int nl = tid & 63;
        int nh = strip*64 + nl;
        int cc = (vt >> 2)*T + tp;
        float nd = rsqrtf(fmaxf((float)g_deg_in[cc*NH + nh], 1.0f));
        ss[tid] = reinterpret_cast<const float*>(g_s4 + (cc*NH + nh))[t] * nd;
    }
    __syncthreads();

    int hq  = tid & 15;
    int row = tid >> 4;

    unsigned long long wr2[8], br2[8];
#pragma unroll
    for (int p = 0; p < 4; p++)
#pragma unroll
        for (int kk = 0; kk < 2; kk++) {
            int h = hq*4 + kk*2;
            wr2[p*2 + kk] = pk2(sW[p*H + h], sW[p*H + h + 1]);
            br2[p*2 + kk] = pk2(sB[p*H + h], sB[p*H + h + 1]);
        }

    const float c1f = 0.5f * (1.0f + NEG);
    const float c2f = 0.5f * (1.0f - NEG);
    const unsigned long long C1 = pk2(c1f, c1f);
    const unsigned long long C2 = pk2(c2f, c2f);
    const unsigned long long ABSM = 0x7FFFFFFF7FFFFFFFull;

#pragma unroll
    for (int j = 0; j < 4; j++) {
        int nl = row + 16*j;
        int nh = strip*64 + nl;
        unsigned long long a0 = 0ull, a1 = 0ull;
#pragma unroll
        for (int p = 0; p < 4; p++) {
            float sv = ss[p*64 + nl];
            unsigned long long sv2 = pk2(sv, sv);
            unsigned long long y0 = fma2(sv2, wr2[p*2 + 0], br2[p*2 + 0]);
            unsigned long long y1 = fma2(sv2, wr2[p*2 + 1], br2[p*2 + 1]);
            a0 = fma2(y0, C1, a0);
            a0 = fma2(y0 & ABSM, C2, a0);
            a1 = fma2(y1, C1, a1);
            a1 = fma2(y1 & ABSM, C2, a1);
        }
        float4 acc;
        upk2(a0, acc.x, acc.y);
        upk2(a1, acc.z, acc.w);
        reinterpret_cast<float4*>(out)[(nh*16 + vt)*16 + hq] = acc;
    }
}

// ================= kernels =================

// K1: zero all accumulators
__global__ void k_init() {
    int tid0   = blockIdx.x * blockDim.x + threadIdx.x;
    int stride = gridDim.x * blockDim.x;
    const int4   z4 = make_int4(0, 0, 0, 0);
    const float4 zf = make_float4(0.f, 0.f, 0.f, 0.f);
    for (int j = tid0; j < C*NS/16; j += stride)
        reinterpret_cast<int4*>(g_deg_out_p)[j] = z4;
    for (int j = tid0; j < C*NH/4; j += stride)
        reinterpret_cast<int4*>(g_deg_in)[j] = z4;
    for (int j = tid0; j < C*NH; j += stride)
        g_s4[j] = zf;
    cudaTriggerProgrammaticLaunchCompletion();
}

// K2: degrees for chain A (combos 0-7)
__global__ void __launch_bounds__(256, 8) k_degA(const int4* __restrict__ src4,
                                                 const int4* __restrict__ dst4) {
    int i = blockIdx.x * blockDim.x + threadIdx.x;
    bool act = i < HQUADS;
    int4 s, d;
    if (act) { s = src4[i]; d = dst4[i]; }
    cudaGridDependencySynchronize();
    if (act) deg_body(i, s, d);
    cudaTriggerProgrammaticLaunchCompletion();
}

// K3: degrees for chain B (combos 8-15)  ||  xn for chain A (v 0-1)
__global__ void __launch_bounds__(256) k_degB_xnA(const int4* __restrict__ src4,
                                                  const int4* __restrict__ dst4,
                                                  const float* __restrict__ x) {
    int bid = blockIdx.x, tid = threadIdx.x;
    if (bid < HB) {
        int i = bid*256 + tid;
        bool act = i < HQUADS;
        int qi = HQUADS + i;
        int4 s, d;
        if (act) { s = src4[qi]; d = dst4[qi]; }
        cudaGridDependencySynchronize();
        if (act) deg_body(qi, s, d);
    } else {
        int j = (bid - HB)*256 + tid;
        bool act = j < HNODES;
        float4 xv = make_float4(0,0,0,0);
        if (act) {
            int v = j / NS, s = j % NS;
            xv.x = fixnum(x[(v*T + 0)*NS + s]);
            xv.y = fixnum(x[(v*T + 1)*NS + s]);
            xv.z = fixnum(x[(v*T + 2)*NS + s]);
            xv.w = fixnum(x[(v*T + 3)*NS + s]);
        }
        cudaGridDependencySynchronize();
        if (act) xn_body(j, 0, xv);
    }
    cudaTriggerProgrammaticLaunchCompletion();
}

// K4: scatter for chain A  ||  xn for chain B (v 2-3)
__global__ void __launch_bounds__(256) k_scatA_xnB(const int4* __restrict__ src4,
                                                   const int4* __restrict__ dst4,
                                                   const float* __restrict__ x) {
    int bid = blockIdx.x, tid = threadIdx.x;
    if (bid < HB) {
        int i = bid*256 + tid;
        bool act = i < HQUADS;
        int4 s, d;
        if (act) { s = src4[i]; d = dst4[i]; }
        cudaGridDependencySynchronize();
        if (act) scatter_body(i, s, d);
    } else {
        int j = (bid - HB)*256 + tid;
        bool act = j < HNODES;
        float4 xv = make_float4(0,0,0,0);
        if (act) {
            int v = 2 + j / NS, s = j % NS;
            xv.x = fixnum(x[(v*T + 0)*NS + s]);
            xv.y = fixnum(x[(v*T + 1)*NS + s]);
            xv.z = fixnum(x[(v*T + 2)*NS + s]);
            xv.w = fixnum(x[(v*T + 3)*NS + s]);
        }
        cudaGridDependencySynchronize();
        if (act) xn_body(j, 2, xv);
    }
    cudaTriggerProgrammaticLaunchCompletion();
}

// K5: scatter for chain B  ||  epilogue for chain A (vt 0-7)
__global__ void __launch_bounds__(256) k_scatB_epiA(const int4* __restrict__ src4,
                                                    const int4* __restrict__ dst4,
                                                    const float* __restrict__ Wp,
                                                    const float* __restrict__ Bp,
                                                    float* __restrict__ out) {
    int bid = blockIdx.x, tid = threadIdx.x;
    if (bid < HB) {
        int i = bid*256 + tid;
        bool act = i < HQUADS;
        int qi = HQUADS + i;
        int4 s, d;
        if (act) { s = src4[qi]; d = dst4[qi]; }
        cudaGridDependencySynchronize();
        if (act) scatter_body(qi, s, d);
    } else {
        int sub = bid - HB;            // 0..1535
        int vt = sub & 7;              // vt 0..7 (v 0-1)
        int strip = sub >> 3;          // 0..191
        int v = vt >> 2;
        float wv = Wp[v*(T*H) + tid];
        float bv = Bp[v*(T*H) + tid];
        cudaGridDependencySynchronize();
        epi_body(vt, strip, tid, wv, bv, out);
    }
    cudaTriggerProgrammaticLaunchCompletion();
}

// K6: epilogue for chain B (vt 8-15)
__global__ void __launch_bounds__(256) k_epiB(const float* __restrict__ Wp,
                                              const float* __restrict__ Bp,
                                              float* __restrict__ out) {
    int bid = blockIdx.x, tid = threadIdx.x;
    int vt = 8 + (bid & 7);            // vt 8..15 (v 2-3)
    int strip = bid >> 3;              // 0..191
    int v = vt >> 2;
    float wv = Wp[v*(T*H) + tid];
    float bv = Bp[v*(T*H) + tid];
    cudaGridDependencySynchronize();
    epi_body(vt, strip, tid, wv, bv, out);
    cudaTriggerProgrammaticLaunchCompletion();
}

// ---------------- PDL launch helper ----------------
template <typename F, typename... Args>
static inline void launch_pdl(F* k, dim3 grid, dim3 block, Args... args) {
    cudaLaunchConfig_t cfg = {};
    cfg.gridDim = grid;
    cfg.blockDim = block;
    cfg.dynamicSmemBytes = 0;
    cfg.stream = 0;
    cudaLaunchAttribute at[1];
    at[0].id = cudaLaunchAttributeProgrammaticStreamSerialization;
    at[0].val.programmaticStreamSerializationAllowed = 1;
    cfg.attrs = at;
    cfg.numAttrs = 1;
    cudaLaunchKernelEx(&cfg, k, args...);
}

// ---------------- launcher ----------------
extern "C" void kernel_launch(void* const* d_in, const int* in_sizes, int n_in,
                              void* d_out, int out_size) {
    const float* x   = (const float*)d_in[0];   // [V,T,NS]
    const float* Wp  = (const float*)d_in[1];   // [V,T,H]
    const float* Bp  = (const float*)d_in[2];   // [V,T,H]
    const int*   src = (const int*)  d_in[3];   // [V,T,E]
    const int*   dst = (const int*)  d_in[4];   // [V,T,E]
    float* out = (float*)d_out;                 // [NH,V,T,H]
    (void)in_sizes; (void)n_in; (void)out_size;

    const int4* src4 = (const int4*)src;
    const int4* dst4 = (const int4*)dst;

    k_init<<<592, 256>>>();
    launch_pdl(k_degA,       dim3(HB),          dim3(256), src4, dst4);
    launch_pdl(k_degB_xnA,   dim3(HB + HB),     dim3(256), src4, dst4, x);
    launch_pdl(k_scatA_xnB,  dim3(HB + HB),     dim3(256), src4, dst4, x);
    launch_pdl(k_scatB_epiA, dim3(HB + EPIHB),  dim3(256), src4, dst4, Wp, Bp, out);
    launch_pdl(k_epiB,       dim3(EPIHB),       dim3(256), Wp, Bp, out);
}